// round 1
// baseline (speedup 1.0000x reference)
#include <cuda_runtime.h>
#include <cstdint>

// LSTM cell, fused:  z = [x|h] @ [Wx;Wh] + bx + bh ; gates ; C_new, h_new
// B=32768, D_IN=512, D_H=512, K_total=1024, N_total=2048 (4 gates x 512)
//
// CTA tile: 128 rows x (4 gates x 32 cols) = 128x128 GEMM tile whose 4
// 32-col gate blocks are the SAME hidden indices j in [n0, n0+32), so the
// LSTM epilogue fuses in shared memory with no global z scratch.
// TF32 mma.sync m16n8k8, fp32 accumulate, cvt.rna rounding at smem staging.

#define BDIM 32768
#define DIN 512
#define DH 512
#define NTOT 2048
#define KTOT 1024

#define BM 128
#define BK 32
#define GN 32            // cols per gate per CTA
#define BN 128           // 4 * GN
#define NKT (KTOT / BK)  // 32 k-tiles
#define THREADS 256

// shared memory layout (floats)
#define LDA 36
#define LDB 132
#define LDZ 132
#define A_ELEMS (2 * BM * LDA)          // 9216
#define B_ELEMS (2 * BK * LDB)          // 8448
#define SMEM_FLOATS (A_ELEMS + B_ELEMS) // 17664
#define SMEM_BYTES (SMEM_FLOATS * 4)    // 70656
// epilogue reuses smem from offset 0: BM*LDZ = 16896 floats = 67584 B < 70656 ✓

__device__ __forceinline__ uint32_t f2tf32(float f) {
    uint32_t r;
    asm("cvt.rna.tf32.f32 %0, %1;" : "=r"(r) : "f"(f));
    return r;
}

__device__ __forceinline__ void mma_tf32(float d[4], const uint32_t a[4],
                                         const uint32_t b[2], const float c[4]) {
    asm volatile(
        "mma.sync.aligned.m16n8k8.row.col.f32.tf32.tf32.f32 "
        "{%0,%1,%2,%3}, {%4,%5,%6,%7}, {%8,%9}, {%10,%11,%12,%13};\n"
        : "=f"(d[0]), "=f"(d[1]), "=f"(d[2]), "=f"(d[3])
        : "r"(a[0]), "r"(a[1]), "r"(a[2]), "r"(a[3]),
          "r"(b[0]), "r"(b[1]),
          "f"(c[0]), "f"(c[1]), "f"(c[2]), "f"(c[3]));
}

__device__ __forceinline__ float sigm(float x) {
    return 1.0f / (1.0f + __expf(-x));
}
__device__ __forceinline__ float tanh_fast(float x) {
    // tanh(x) = 2*sigmoid(2x) - 1
    return 2.0f / (1.0f + __expf(-2.0f * x)) - 1.0f;
}

__global__ void __launch_bounds__(THREADS, 1)
lstm_kernel(const float* __restrict__ x, const float* __restrict__ Cin,
            const float* __restrict__ h, const float* __restrict__ Wx,
            const float* __restrict__ bx, const float* __restrict__ Wh,
            const float* __restrict__ bh, float* __restrict__ out) {
    extern __shared__ float smem[];
    float* sA = smem;                 // [2][BM][LDA]
    float* sB = smem + A_ELEMS;       // [2][BK][LDB]
    float* zs = smem;                 // [BM][LDZ] (reused after GEMM)

    const int tid = threadIdx.x;
    const int warp = tid >> 5;
    const int lane = tid & 31;
    const int wm = warp & 3;   // 4 warps along M
    const int wn = warp >> 2;  // 2 warps along N
    const int gid = lane >> 2;
    const int tig = lane & 3;

    const int rowBase = blockIdx.y * BM;  // global batch row base
    const int nBase = blockIdx.x * GN;    // hidden index base (per gate)

    float acc[2][8][4];
#pragma unroll
    for (int mt = 0; mt < 2; ++mt)
#pragma unroll
        for (int nt = 0; nt < 8; ++nt)
#pragma unroll
            for (int c = 0; c < 4; ++c) acc[mt][nt][c] = 0.0f;

    float4 ar[4], br[4];

    // --- staging helpers ---
    auto loadTile = [&](int kt) {
        const int kg = kt * BK;
        const float* srcA = (kg < DIN) ? (x + kg) : (h + (kg - DIN));
        const float* srcW =
            (kg < DIN) ? (Wx + (size_t)kg * NTOT) : (Wh + (size_t)(kg - DIN) * NTOT);
#pragma unroll
        for (int i = 0; i < 4; ++i) {
            const int id4 = tid + i * THREADS;  // 0..1023
            // A: 128 rows x 32 cols, 8 float4 per row
            const int r = id4 >> 3;
            const int c = (id4 & 7) << 2;
            ar[i] = *(const float4*)(srcA + (size_t)(rowBase + r) * DIN + c);
            // B: 32 k-rows x 128 cols (4 gate blocks of 32)
            const int rk = id4 >> 5;
            const int ct = (id4 & 31) << 2;  // tile col, mult of 4
            const int gate = ct >> 5;
            const int j = ct & 31;
            br[i] = *(const float4*)(srcW + (size_t)rk * NTOT + gate * DH + nBase + j);
        }
    };

    auto storeTile = [&](int buf) {
#pragma unroll
        for (int i = 0; i < 4; ++i) {
            const int id4 = tid + i * THREADS;
            const int r = id4 >> 3;
            const int c = (id4 & 7) << 2;
            uint4 av = make_uint4(f2tf32(ar[i].x), f2tf32(ar[i].y),
                                  f2tf32(ar[i].z), f2tf32(ar[i].w));
            *(uint4*)(sA + buf * BM * LDA + r * LDA + c) = av;
            const int rk = id4 >> 5;
            const int ct = (id4 & 31) << 2;
            uint4 bv = make_uint4(f2tf32(br[i].x), f2tf32(br[i].y),
                                  f2tf32(br[i].z), f2tf32(br[i].w));
            *(uint4*)(sB + buf * BK * LDB + rk * LDB + ct) = bv;
        }
    };

    auto compute = [&](int buf) {
        const float* Ab = sA + buf * BM * LDA;
        const float* Bb = sB + buf * BK * LDB;
#pragma unroll
        for (int ks = 0; ks < 4; ++ks) {
            const int k0 = ks * 8;
            uint32_t af[2][4];
#pragma unroll
            for (int mt = 0; mt < 2; ++mt) {
                const int r0 = wm * 32 + mt * 16 + gid;
                af[mt][0] = __float_as_uint(Ab[(r0) * LDA + k0 + tig]);
                af[mt][1] = __float_as_uint(Ab[(r0 + 8) * LDA + k0 + tig]);
                af[mt][2] = __float_as_uint(Ab[(r0) * LDA + k0 + tig + 4]);
                af[mt][3] = __float_as_uint(Ab[(r0 + 8) * LDA + k0 + tig + 4]);
            }
            uint32_t bf[8][2];
#pragma unroll
            for (int nt = 0; nt < 8; ++nt) {
                const int cc = wn * 64 + nt * 8 + gid;
                bf[nt][0] = __float_as_uint(Bb[(k0 + tig) * LDB + cc]);
                bf[nt][1] = __float_as_uint(Bb[(k0 + tig + 4) * LDB + cc]);
            }
#pragma unroll
            for (int mt = 0; mt < 2; ++mt)
#pragma unroll
                for (int nt = 0; nt < 8; ++nt)
                    mma_tf32(acc[mt][nt], af[mt], bf[nt], acc[mt][nt]);
        }
    };

    // --- pipelined main loop ---
    loadTile(0);
    storeTile(0);
    __syncthreads();
#pragma unroll 1
    for (int kt = 0; kt < NKT; ++kt) {
        const int buf = kt & 1;
        if (kt < NKT - 1) loadTile(kt + 1);
        compute(buf);
        if (kt < NKT - 1) {
            storeTile((kt + 1) & 1);
            __syncthreads();
        }
    }

    // --- epilogue: accum -> zs smem, then LSTM gates ---
    __syncthreads();  // all reads of sA/sB done before zs overwrite
#pragma unroll
    for (int mt = 0; mt < 2; ++mt)
#pragma unroll
        for (int nt = 0; nt < 8; ++nt)
#pragma unroll
            for (int c = 0; c < 4; ++c) {
                const int r = wm * 32 + mt * 16 + gid + ((c >= 2) ? 8 : 0);
                const int cc = wn * 64 + nt * 8 + tig * 2 + (c & 1);
                zs[r * LDZ + cc] = acc[mt][nt][c];
            }
    __syncthreads();

    const float* outC = out;
    float* outH = out + (size_t)BDIM * DH;
#pragma unroll
    for (int i = 0; i < 16; ++i) {
        const int idx = tid + i * THREADS;  // 0..4095
        const int m = idx >> 5;             // 0..127
        const int j = idx & 31;             // 0..31
        const int col = nBase + j;          // hidden index
        const float bi = bx[0 * DH + col] + bh[0 * DH + col];
        const float bf_ = bx[1 * DH + col] + bh[1 * DH + col];
        const float bo = bx[2 * DH + col] + bh[2 * DH + col];
        const float bg = bx[3 * DH + col] + bh[3 * DH + col];
        const float zi = zs[m * LDZ + j] + bi;
        const float zf = zs[m * LDZ + 32 + j] + bf_;
        const float zo = zs[m * LDZ + 64 + j] + bo;
        const float zg = zs[m * LDZ + 96 + j] + bg;
        const float ig = sigm(zi);
        const float fg = sigm(zf);
        const float og = sigm(zo);
        const float gg = tanh_fast(zg);
        const size_t goff = (size_t)(rowBase + m) * DH + col;
        const float cnew = fg * Cin[goff] + ig * gg;
        const float hnew = og * tanh_fast(cnew);
        ((float*)outC)[goff] = cnew;
        outH[goff] = hnew;
    }
}

extern "C" void kernel_launch(void* const* d_in, const int* in_sizes, int n_in,
                              void* d_out, int out_size) {
    const float* x = (const float*)d_in[0];
    const float* C = (const float*)d_in[1];
    const float* h = (const float*)d_in[2];
    const float* Wx = (const float*)d_in[3];
    const float* bx = (const float*)d_in[4];
    const float* Wh = (const float*)d_in[5];
    const float* bh = (const float*)d_in[6];
    float* out = (float*)d_out;

    cudaFuncSetAttribute(lstm_kernel, cudaFuncAttributeMaxDynamicSharedMemorySize,
                         SMEM_BYTES);
    dim3 grid(DH / GN, BDIM / BM);  // (16, 256)
    lstm_kernel<<<grid, THREADS, SMEM_BYTES>>>(x, C, h, Wx, bx, Wh, bh, out);
}

// round 3
// speedup vs baseline: 1.4609x; 1.4609x over previous
#include <cuda_runtime.h>
#include <cstdint>

// Fused LSTM cell, sm_103 family-generic path (no tcgen05 on this toolchain).
// Pass 1: cvt.rna fp32->tf32 once:  Ascr = [x|h]  (32768 x 1024, row-major)
//         Bscr = [Wx;Wh] gate-permuted ([K=1024][N=2048], CTA cols contiguous)
// Pass 2: 128x128x1024 GEMM per CTA, cp.async 3-stage pipeline,
//         mma.sync.m16n8k8.tf32, fused LSTM gate epilogue. 2 CTAs/SM.

#define BATCH 32768
#define DH 512
#define KTOT 1024
#define NTOT 2048

#define BM 128
#define BN 128
#define BK 32
#define KTILES (KTOT / BK)  // 32
#define STAGES 3
#define THREADS 256

#define LDA 36
#define LDB 132
#define LDZ 132
#define A_STG (BM * LDA)                  // 4608 floats
#define B_STG (BK * LDB)                  // 4224 floats
#define STG_FLOATS (A_STG + B_STG)        // 8832
#define SMEM_BYTES (STAGES * STG_FLOATS * 4)  // 105984
// epilogue zs reuse: BM*LDZ*4 = 67584 <= 105984  ok

// ---------------- device scratch ----------------
__device__ uint32_t Ascr[(size_t)BATCH * KTOT];  // 128 MB
__device__ uint32_t Bscr[(size_t)KTOT * NTOT];   // 8 MB

__device__ __forceinline__ uint32_t f2tf32(float f) {
    uint32_t r;
    asm("cvt.rna.tf32.f32 %0, %1;" : "=r"(r) : "f"(f));
    return r;
}
__device__ __forceinline__ uint32_t smem_u32(const void* p) {
    uint32_t a;
    asm("{ .reg .u64 t; cvta.to.shared.u64 t, %1; cvt.u32.u64 %0, t; }"
        : "=r"(a) : "l"(p));
    return a;
}
__device__ __forceinline__ void cp16(uint32_t sm, const void* g) {
    asm volatile("cp.async.cg.shared.global [%0], [%1], 16;"
                 :: "r"(sm), "l"(g) : "memory");
}
__device__ __forceinline__ void cp_commit() {
    asm volatile("cp.async.commit_group;" ::: "memory");
}

__device__ __forceinline__ void mma_tf32(float d[4], const uint32_t a[4],
                                         const uint32_t b[2], const float c[4]) {
    asm volatile(
        "mma.sync.aligned.m16n8k8.row.col.f32.tf32.tf32.f32 "
        "{%0,%1,%2,%3}, {%4,%5,%6,%7}, {%8,%9}, {%10,%11,%12,%13};\n"
        : "=f"(d[0]), "=f"(d[1]), "=f"(d[2]), "=f"(d[3])
        : "r"(a[0]), "r"(a[1]), "r"(a[2]), "r"(a[3]),
          "r"(b[0]), "r"(b[1]),
          "f"(c[0]), "f"(c[1]), "f"(c[2]), "f"(c[3]));
}

__device__ __forceinline__ float sigm(float v) { return 1.0f / (1.0f + __expf(-v)); }
__device__ __forceinline__ float tanh_fast(float v) {
    return 2.0f / (1.0f + __expf(-2.0f * v)) - 1.0f;
}

// ---------------- pass 1 ----------------
__global__ void __launch_bounds__(256) prep_a(const float* __restrict__ x,
                                              const float* __restrict__ h) {
    size_t i = (size_t)blockIdx.x * 256 + threadIdx.x;  // float4 index
    size_t e = i * 4;
    int b = (int)(e >> 10);
    int k = (int)(e & 1023);
    const float* src = (k < 512) ? (x + (size_t)b * 512 + k)
                                 : (h + (size_t)b * 512 + (k - 512));
    float4 v = *(const float4*)src;
    uint4 o = make_uint4(f2tf32(v.x), f2tf32(v.y), f2tf32(v.z), f2tf32(v.w));
    *(uint4*)(Ascr + e) = o;
}

// Bscr[k][n'],  n' = nt*128 + g*32 + j  <-  W[k][g*512 + nt*32 + j]
__global__ void __launch_bounds__(256) prep_b(const float* __restrict__ Wx,
                                              const float* __restrict__ Wh) {
    size_t t = (size_t)blockIdx.x * 256 + threadIdx.x;  // float4 index
    size_t e = t * 4;
    int k = (int)(e >> 11);
    int np = (int)(e & 2047);
    int nt = np >> 7;
    int g = (np >> 5) & 3;
    int j = np & 31;
    int col = g * 512 + nt * 32 + j;
    const float* src = (k < 512) ? (Wx + (size_t)k * NTOT + col)
                                 : (Wh + (size_t)(k - 512) * NTOT + col);
    float4 v = *(const float4*)src;
    uint4 o = make_uint4(f2tf32(v.x), f2tf32(v.y), f2tf32(v.z), f2tf32(v.w));
    *(uint4*)(Bscr + e) = o;
}

// ---------------- pass 2 ----------------
__global__ void __launch_bounds__(THREADS, 2)
lstm_gemm(const float* __restrict__ Cin, const float* __restrict__ bx,
          const float* __restrict__ bh, float* __restrict__ out) {
    extern __shared__ float smem[];
    const uint32_t sbase = smem_u32(smem);

    const int tid = threadIdx.x;
    const int warp = tid >> 5;
    const int lane = tid & 31;
    const int wm = warp & 3;
    const int wn = warp >> 2;
    const int gid = lane >> 2;
    const int tig = lane & 3;

    const int mBase = blockIdx.y * BM;
    const int nt = blockIdx.x;

    float acc[2][8][4];
#pragma unroll
    for (int mt = 0; mt < 2; ++mt)
#pragma unroll
        for (int n = 0; n < 8; ++n)
#pragma unroll
            for (int c = 0; c < 4; ++c) acc[mt][n][c] = 0.0f;

    // per-thread load coordinates (4 float4 each for A and B)
    const int rA = tid >> 3;           // 0..31  (A rows, +32 per step)
    const int cA = (tid & 7) << 2;     // col within 32
    const int rB = tid >> 5;           // 0..7   (B k-rows, +8 per step)
    const int cB = (lane) << 2;        // col within 128

    auto issue = [&](int kt) {
        const uint32_t kg = kt * BK;
        const int s = kt % STAGES;
        const uint32_t sa = sbase + (uint32_t)(s * STG_FLOATS) * 4u;
        const uint32_t sb = sa + A_STG * 4u;
        const uint32_t* gA = Ascr + (size_t)(mBase + rA) * KTOT + kg + cA;
        const uint32_t* gB = Bscr + (size_t)(kg + rB) * NTOT + nt * BN + cB;
#pragma unroll
        for (int i = 0; i < 4; ++i) {
            cp16(sa + ((rA + i * 32) * LDA + cA) * 4u, gA + (size_t)i * 32 * KTOT);
            cp16(sb + ((rB + i * 8) * LDB + cB) * 4u, gB + (size_t)i * 8 * NTOT);
        }
        cp_commit();
    };

    auto compute = [&](int s) {
        const float* Ab = smem + s * STG_FLOATS;
        const float* Bb = Ab + A_STG;
#pragma unroll
        for (int ks = 0; ks < 4; ++ks) {
            const int k0 = ks * 8;
            uint32_t af[2][4];
#pragma unroll
            for (int mt = 0; mt < 2; ++mt) {
                const int r0 = wm * 32 + mt * 16 + gid;
                af[mt][0] = __float_as_uint(Ab[(r0) * LDA + k0 + tig]);
                af[mt][1] = __float_as_uint(Ab[(r0 + 8) * LDA + k0 + tig]);
                af[mt][2] = __float_as_uint(Ab[(r0) * LDA + k0 + tig + 4]);
                af[mt][3] = __float_as_uint(Ab[(r0 + 8) * LDA + k0 + tig + 4]);
            }
            uint32_t bf[8][2];
#pragma unroll
            for (int n = 0; n < 8; ++n) {
                const int cc = wn * 64 + n * 8 + gid;
                bf[n][0] = __float_as_uint(Bb[(k0 + tig) * LDB + cc]);
                bf[n][1] = __float_as_uint(Bb[(k0 + tig + 4) * LDB + cc]);
            }
#pragma unroll
            for (int mt = 0; mt < 2; ++mt)
#pragma unroll
                for (int n = 0; n < 8; ++n)
                    mma_tf32(acc[mt][n], af[mt], bf[n], acc[mt][n]);
        }
    };

    // prologue: stages 0,1
    issue(0);
    issue(1);

#pragma unroll 1
    for (int kt = 0; kt < KTILES; ++kt) {
        if (kt == KTILES - 1) {
            asm volatile("cp.async.wait_group 0;" ::: "memory");
        } else {
            asm volatile("cp.async.wait_group 1;" ::: "memory");
        }
        __syncthreads();
        if (kt + STAGES - 1 < KTILES) issue(kt + STAGES - 1);
        compute(kt % STAGES);
    }

    // ---------------- epilogue ----------------
    __syncthreads();  // all warps done reading stages before zs overwrite
    float* zs = smem;
#pragma unroll
    for (int mt = 0; mt < 2; ++mt)
#pragma unroll
        for (int n = 0; n < 8; ++n)
#pragma unroll
            for (int c = 0; c < 4; ++c) {
                const int r = wm * 32 + mt * 16 + gid + ((c >= 2) ? 8 : 0);
                const int cc = wn * 64 + n * 8 + tig * 2 + (c & 1);
                zs[r * LDZ + cc] = acc[mt][n][c];
            }
    __syncthreads();

    float* outH = out + (size_t)BATCH * DH;
#pragma unroll 1
    for (int i = 0; i < 16; ++i) {
        const int idx = tid + i * THREADS;  // 0..4095
        const int m = idx >> 5;
        const int j = idx & 31;
        const int hj = nt * 32 + j;
        const float zi = zs[m * LDZ + j]      + __ldg(bx + hj)        + __ldg(bh + hj);
        const float zf = zs[m * LDZ + 32 + j] + __ldg(bx + 512 + hj)  + __ldg(bh + 512 + hj);
        const float zo = zs[m * LDZ + 64 + j] + __ldg(bx + 1024 + hj) + __ldg(bh + 1024 + hj);
        const float zg = zs[m * LDZ + 96 + j] + __ldg(bx + 1536 + hj) + __ldg(bh + 1536 + hj);
        const float ig = sigm(zi);
        const float fg = sigm(zf);
        const float og = sigm(zo);
        const float gg = tanh_fast(zg);
        const size_t goff = (size_t)(mBase + m) * DH + hj;
        const float cnew = fg * Cin[goff] + ig * gg;
        out[goff] = cnew;
        outH[goff] = og * tanh_fast(cnew);
    }
}

extern "C" void kernel_launch(void* const* d_in, const int* in_sizes, int n_in,
                              void* d_out, int out_size) {
    const float* x = (const float*)d_in[0];
    const float* C = (const float*)d_in[1];
    const float* h = (const float*)d_in[2];
    const float* Wx = (const float*)d_in[3];
    const float* bx = (const float*)d_in[4];
    const float* Wh = (const float*)d_in[5];
    const float* bh = (const float*)d_in[6];
    float* out = (float*)d_out;

    cudaFuncSetAttribute(lstm_gemm, cudaFuncAttributeMaxDynamicSharedMemorySize,
                         SMEM_BYTES);

    prep_a<<<(size_t)BATCH * KTOT / 4 / 256, 256>>>(x, h);
    prep_b<<<(size_t)KTOT * NTOT / 4 / 256, 256>>>(Wx, Wh);
    dim3 grid(NTOT / BN, BATCH / BM);  // (16, 256)
    lstm_gemm<<<grid, THREADS, SMEM_BYTES>>>(C, bx, bh, out);
}

// round 4
// speedup vs baseline: 2.6588x; 1.8199x over previous
#include <cuda_runtime.h>
#include <cuda_fp16.h>
#include <cstdint>

// Fused LSTM cell, sm_103 family-generic (no tcgen05 in this toolchain).
// Pass 1: fp32 -> fp16(rn) once.  AscrH = [x|h] (32768 x 1024 row-major).
//         BscrH = [Wx;Wh]^T gate-permuted: [N'=2048][K=1024], where
//         n' = nt*128 + g*32 + j  <->  weight col g*512 + nt*32 + j.
// Pass 2: 128x128x1024 GEMM per CTA, cp.async 3-stage pipeline,
//         ldmatrix.x4 fragments, mma.sync.m16n8k16.f16 (fp32 accum),
//         fused LSTM gate epilogue. 2 CTAs/SM.

#define BATCH 32768
#define DH 512
#define KTOT 1024
#define NTOT 2048

#define BM 128
#define BN 128
#define BK 64
#define KTILES (KTOT / BK)  // 16
#define STAGES 3
#define THREADS 256

#define ROWP 72                       // halves per smem row (64 + 8 pad)
#define TILE_H (128 * ROWP)           // 9216 halves per A/B tile
#define STG_BYTES (2 * TILE_H * 2)    // 36864 B (A tile + B tile)
#define SMEM_BYTES (STAGES * STG_BYTES)  // 110592
#define LDZ 132
// epilogue zs reuse: 128*132*4 = 67584 <= 110592 ok

// ---------------- device scratch ----------------
__device__ __half AscrH[(size_t)BATCH * KTOT];  // 64 MB
__device__ __half BscrH[(size_t)NTOT * KTOT];   // 4 MB

__device__ __forceinline__ uint32_t smem_u32(const void* p) {
    uint32_t a;
    asm("{ .reg .u64 t; cvta.to.shared.u64 t, %1; cvt.u32.u64 %0, t; }"
        : "=r"(a) : "l"(p));
    return a;
}
__device__ __forceinline__ void cp16(uint32_t sm, const void* g) {
    asm volatile("cp.async.cg.shared.global [%0], [%1], 16;"
                 :: "r"(sm), "l"(g) : "memory");
}
__device__ __forceinline__ void ldsm_x4(uint32_t& r0, uint32_t& r1,
                                        uint32_t& r2, uint32_t& r3,
                                        uint32_t addr) {
    asm volatile("ldmatrix.sync.aligned.m8n8.x4.shared.b16 {%0,%1,%2,%3}, [%4];"
                 : "=r"(r0), "=r"(r1), "=r"(r2), "=r"(r3) : "r"(addr));
}
__device__ __forceinline__ void mma_f16(float d[4], const uint32_t a[4],
                                        const uint32_t b[2], const float c[4]) {
    asm volatile(
        "mma.sync.aligned.m16n8k16.row.col.f32.f16.f16.f32 "
        "{%0,%1,%2,%3}, {%4,%5,%6,%7}, {%8,%9}, {%10,%11,%12,%13};\n"
        : "=f"(d[0]), "=f"(d[1]), "=f"(d[2]), "=f"(d[3])
        : "r"(a[0]), "r"(a[1]), "r"(a[2]), "r"(a[3]),
          "r"(b[0]), "r"(b[1]),
          "f"(c[0]), "f"(c[1]), "f"(c[2]), "f"(c[3]));
}

__device__ __forceinline__ float sigm(float v) { return 1.0f / (1.0f + __expf(-v)); }
__device__ __forceinline__ float tanh_fast(float v) {
    return 2.0f / (1.0f + __expf(-2.0f * v)) - 1.0f;
}

// ---------------- pass 1 ----------------
__global__ void __launch_bounds__(256) prep_a(const float* __restrict__ x,
                                              const float* __restrict__ h) {
    size_t i = (size_t)blockIdx.x * 256 + threadIdx.x;  // float4 index
    size_t e = i * 4;
    int b = (int)(e >> 10);
    int k = (int)(e & 1023);
    const float* src = (k < 512) ? (x + (size_t)b * 512 + k)
                                 : (h + (size_t)b * 512 + (k - 512));
    float4 v = *(const float4*)src;
    __half2 h0 = __floats2half2_rn(v.x, v.y);
    __half2 h1 = __floats2half2_rn(v.z, v.w);
    uint2 o = make_uint2(*(uint32_t*)&h0, *(uint32_t*)&h1);
    *(uint2*)(AscrH + e) = o;
}

// BscrH[n'][k] = W[k][col(n')],  n' = nt*128 + g*32 + j, col = g*512 + nt*32 + j
__global__ void __launch_bounds__(256) prep_b(const float* __restrict__ Wx,
                                              const float* __restrict__ Wh) {
    size_t t = (size_t)blockIdx.x * 256 + threadIdx.x;  // 524288 threads
    int np = (int)(t >> 8);          // n' 0..2047
    int kb = (int)(t & 255) * 4;     // k base
    int nt = np >> 7;
    int g = (np >> 5) & 3;
    int j = np & 31;
    int col = g * 512 + nt * 32 + j;
    const float* src = (kb < 512) ? (Wx + (size_t)kb * NTOT + col)
                                  : (Wh + (size_t)(kb - 512) * NTOT + col);
    float v0 = src[0];
    float v1 = src[NTOT];
    float v2 = src[2 * NTOT];
    float v3 = src[3 * NTOT];
    __half2 h0 = __floats2half2_rn(v0, v1);
    __half2 h1 = __floats2half2_rn(v2, v3);
    uint2 o = make_uint2(*(uint32_t*)&h0, *(uint32_t*)&h1);
    *(uint2*)(BscrH + (size_t)np * KTOT + kb) = o;
}

// ---------------- pass 2 ----------------
__global__ void __launch_bounds__(THREADS, 2)
lstm_gemm(const float* __restrict__ Cin, const float* __restrict__ bx,
          const float* __restrict__ bh, float* __restrict__ out) {
    extern __shared__ float smem[];
    const uint32_t sbase = smem_u32(smem);

    const int tid = threadIdx.x;
    const int warp = tid >> 5;
    const int lane = tid & 31;
    const int wm = warp & 3;
    const int wn = warp >> 2;
    const int gid = lane >> 2;
    const int tig = lane & 3;

    const int mBase = blockIdx.y * BM;
    const int nt = blockIdx.x;

    float acc[2][8][4];
#pragma unroll
    for (int mt = 0; mt < 2; ++mt)
#pragma unroll
        for (int n = 0; n < 8; ++n)
#pragma unroll
            for (int c = 0; c < 4; ++c) acc[mt][n][c] = 0.0f;

    // cp.async coordinates: chunk c = tid + i*256 (i<4); row = c>>3, 16B col = c&7
    const int ldR = tid >> 3;             // 0..31, +32 per i
    const int ldC = tid & 7;              // 16B chunk in row

    const __half* gA0 = AscrH + (size_t)(mBase + ldR) * KTOT + ldC * 8;
    const __half* gB0 = BscrH + (size_t)(nt * BN + ldR) * KTOT + ldC * 8;

    auto issue = [&](int kt) {
        const int s = kt % STAGES;
        const uint32_t sa = sbase + (uint32_t)s * STG_BYTES;
        const uint32_t sb = sa + TILE_H * 2;
        const uint32_t soff = (uint32_t)(ldR * ROWP + ldC * 8) * 2;
        const size_t kg = (size_t)kt * BK;
#pragma unroll
        for (int i = 0; i < 4; ++i) {
            cp16(sa + soff + i * 32 * ROWP * 2, gA0 + kg + (size_t)i * 32 * KTOT);
            cp16(sb + soff + i * 32 * ROWP * 2, gB0 + kg + (size_t)i * 32 * KTOT);
        }
        asm volatile("cp.async.commit_group;" ::: "memory");
    };

    // ldmatrix lane address offsets (bytes): rows (lane&15), k-half (lane>>4)*8
    const uint32_t lmOff = (uint32_t)((lane & 15) * ROWP + (lane >> 4) * 8) * 2;
    const uint32_t aWarp = (uint32_t)(wm * 32 * ROWP) * 2 + lmOff;
    const uint32_t bWarp = (uint32_t)(wn * 64 * ROWP) * 2 + lmOff;

    auto compute = [&](int s) {
        const uint32_t sa = sbase + (uint32_t)s * STG_BYTES;
        const uint32_t sb = sa + TILE_H * 2;
#pragma unroll
        for (int ks = 0; ks < 4; ++ks) {
            const uint32_t kOff = ks * 32;  // 16 halves = 32 B
            uint32_t a[2][4];
#pragma unroll
            for (int mt = 0; mt < 2; ++mt)
                ldsm_x4(a[mt][0], a[mt][1], a[mt][2], a[mt][3],
                        sa + aWarp + (uint32_t)(mt * 16 * ROWP) * 2 + kOff);
            uint32_t bf[8][2];
#pragma unroll
            for (int p = 0; p < 4; ++p) {
                uint32_t r0, r1, r2, r3;
                ldsm_x4(r0, r1, r2, r3,
                        sb + bWarp + (uint32_t)(p * 16 * ROWP) * 2 + kOff);
                bf[2 * p][0] = r0;     bf[2 * p][1] = r2;
                bf[2 * p + 1][0] = r1; bf[2 * p + 1][1] = r3;
            }
#pragma unroll
            for (int mt = 0; mt < 2; ++mt)
#pragma unroll
                for (int n = 0; n < 8; ++n)
                    mma_f16(acc[mt][n], a[mt], bf[n], acc[mt][n]);
        }
    };

    issue(0);
    issue(1);

#pragma unroll 1
    for (int kt = 0; kt < KTILES; ++kt) {
        if (kt == KTILES - 1) {
            asm volatile("cp.async.wait_group 0;" ::: "memory");
        } else {
            asm volatile("cp.async.wait_group 1;" ::: "memory");
        }
        __syncthreads();
        if (kt + STAGES - 1 < KTILES) issue(kt + STAGES - 1);
        compute(kt % STAGES);
    }

    // ---------------- epilogue ----------------
    __syncthreads();
    float* zs = smem;
#pragma unroll
    for (int mt = 0; mt < 2; ++mt)
#pragma unroll
        for (int n = 0; n < 8; ++n)
#pragma unroll
            for (int c = 0; c < 4; ++c) {
                const int r = wm * 32 + mt * 16 + gid + ((c >= 2) ? 8 : 0);
                const int cc = wn * 64 + n * 8 + tig * 2 + (c & 1);
                zs[r * LDZ + cc] = acc[mt][n][c];
            }
    __syncthreads();

    float* outH = out + (size_t)BATCH * DH;
#pragma unroll 1
    for (int i = 0; i < 16; ++i) {
        const int idx = tid + i * THREADS;  // 0..4095
        const int m = idx >> 5;
        const int j = idx & 31;
        const int hj = nt * 32 + j;
        const float zi = zs[m * LDZ + j]      + __ldg(bx + hj)        + __ldg(bh + hj);
        const float zf = zs[m * LDZ + 32 + j] + __ldg(bx + 512 + hj)  + __ldg(bh + 512 + hj);
        const float zo = zs[m * LDZ + 64 + j] + __ldg(bx + 1024 + hj) + __ldg(bh + 1024 + hj);
        const float zg = zs[m * LDZ + 96 + j] + __ldg(bx + 1536 + hj) + __ldg(bh + 1536 + hj);
        const float ig = sigm(zi);
        const float fg = sigm(zf);
        const float og = sigm(zo);
        const float gg = tanh_fast(zg);
        const size_t goff = (size_t)(mBase + m) * DH + hj;
        const float cnew = fg * Cin[goff] + ig * gg;
        out[goff] = cnew;
        outH[goff] = og * tanh_fast(cnew);
    }
}

extern "C" void kernel_launch(void* const* d_in, const int* in_sizes, int n_in,
                              void* d_out, int out_size) {
    const float* x = (const float*)d_in[0];
    const float* C = (const float*)d_in[1];
    const float* h = (const float*)d_in[2];
    const float* Wx = (const float*)d_in[3];
    const float* bx = (const float*)d_in[4];
    const float* Wh = (const float*)d_in[5];
    const float* bh = (const float*)d_in[6];
    float* out = (float*)d_out;

    cudaFuncSetAttribute(lstm_gemm, cudaFuncAttributeMaxDynamicSharedMemorySize,
                         SMEM_BYTES);

    prep_a<<<(size_t)BATCH * KTOT / 4 / 256, 256>>>(x, h);
    prep_b<<<(size_t)NTOT * KTOT / 4 / 256, 256>>>(Wx, Wh);
    dim3 grid(NTOT / BN, BATCH / BM);  // (16, 256)
    lstm_gemm<<<grid, THREADS, SMEM_BYTES>>>(C, bx, bh, out);
}